// round 2
// baseline (speedup 1.0000x reference)
#include <cuda_runtime.h>

#define B_  64
#define D_  128
#define LC  1024
#define LQ  256
#define NEGINF (-1e30f)

// ---------------- scratch (static device arrays; no allocation at runtime) ----------------
static __device__ float g_S [(size_t)B_*LC*LQ];   // raw scores
static __device__ float g_S1[(size_t)B_*LC*LQ];   // softmax over m
static __device__ float g_S2[(size_t)B_*LC*LQ];   // softmax over l
static __device__ float g_A [(size_t)B_*LC*D_];
static __device__ float g_Bv[(size_t)B_*LC*D_];
static __device__ float g_Tp[(size_t)B_*4*LQ*D_]; // split-K partials for T
static __device__ float g_T [(size_t)B_*LQ*D_];
static __device__ float g_c1[B_*LC];
static __device__ float g_q2[B_*LQ];

// ---------------- K1: bias vectors c1[l] = Ct.w1, q2[m] = Qt.w2 ----------------
__global__ void k_bias(const float* __restrict__ C, const float* __restrict__ Q,
                       const float* __restrict__ w) {
    int b = blockIdx.y;
    int seg = blockIdx.x;
    int t = threadIdx.x;
    if (seg < 4) {
        int l = seg * 256 + t;
        const float* Cb = C + (size_t)b * D_ * LC;
        float acc = 0.f;
#pragma unroll 8
        for (int d = 0; d < D_; d++) acc += Cb[(size_t)d * LC + l] * __ldg(w + d);
        g_c1[b * LC + l] = acc;
    } else {
        int m = t;
        const float* Qb = Q + (size_t)b * D_ * LQ;
        float acc = 0.f;
#pragma unroll 8
        for (int d = 0; d < D_; d++) acc += Qb[(size_t)d * LQ + m] * __ldg(w + D_ + d);
        g_q2[b * LQ + m] = acc;
    }
}

// ---------------- generic batched 128x128 tile SGEMM ----------------
// Out(m,n) = sum_k A(m,k)*B(n,k)
// AKF: A element at Ab[m*lda + k] (K-fast) else Ab[k*lda + m] (K-slow)
// BKF: B element at Bb[n*ldb + k] (K-fast) else Bb[k*ldb + n] (K-slow)
// SCW: multiply A element by w3[k] (only used with K-slow A)
// EPI: 0 plain store, 1 add biasR[row] + biasC[col]
template<bool AKF, bool BKF, bool SCW, int EPI>
__global__ __launch_bounds__(256) void gemm128(
    const float* __restrict__ Ag, const float* __restrict__ Bg, float* __restrict__ Cg,
    int lda, int ldb, int ldc, int Kloc, int nsplit,
    long batA, long batB, long batC,
    const float* __restrict__ w3,
    const float* __restrict__ biasR, const float* __restrict__ biasC,
    int biasRs, int biasCs)
{
    __shared__ float As[16][132];
    __shared__ float Bs[16][132];

    const int zb    = blockIdx.z / nsplit;
    const int split = blockIdx.z - zb * nsplit;
    const int k0 = split * Kloc;
    const int m0 = blockIdx.y << 7;
    const int n0 = blockIdx.x << 7;

    const float* Ab = Ag + (size_t)zb * batA;
    const float* Bb = Bg + (size_t)zb * batB;

    const int tid = threadIdx.x;
    const int tx = tid & 15, ty = tid >> 4;

    float acc[8][8];
#pragma unroll
    for (int i = 0; i < 8; i++)
#pragma unroll
        for (int j = 0; j < 8; j++) acc[i][j] = 0.f;

    float4 ra[2], rb[2];

    auto ldGA = [&](int kk0) {
#pragma unroll
        for (int i = 0; i < 2; i++) {
            int f = tid + (i << 8);
            if constexpr (AKF) {
                int mr = f >> 2, kc = (f & 3) << 2;
                ra[i] = *reinterpret_cast<const float4*>(Ab + (size_t)(m0 + mr) * lda + kk0 + kc);
            } else {
                int kr = f >> 5, mc = (f & 31) << 2;
                float4 v = *reinterpret_cast<const float4*>(Ab + (size_t)(kk0 + kr) * lda + m0 + mc);
                if constexpr (SCW) {
                    float wv = __ldg(w3 + kk0 + kr);
                    v.x *= wv; v.y *= wv; v.z *= wv; v.w *= wv;
                }
                ra[i] = v;
            }
        }
    };
    auto ldGB = [&](int kk0) {
#pragma unroll
        for (int i = 0; i < 2; i++) {
            int f = tid + (i << 8);
            if constexpr (BKF) {
                int nr = f >> 2, kc = (f & 3) << 2;
                rb[i] = *reinterpret_cast<const float4*>(Bb + (size_t)(n0 + nr) * ldb + kk0 + kc);
            } else {
                int kr = f >> 5, nc = (f & 31) << 2;
                rb[i] = *reinterpret_cast<const float4*>(Bb + (size_t)(kk0 + kr) * ldb + n0 + nc);
            }
        }
    };
    auto stSA = [&]() {
#pragma unroll
        for (int i = 0; i < 2; i++) {
            int f = tid + (i << 8);
            if constexpr (AKF) {
                int mr = f >> 2, kc = (f & 3) << 2;
                As[kc + 0][mr] = ra[i].x; As[kc + 1][mr] = ra[i].y;
                As[kc + 2][mr] = ra[i].z; As[kc + 3][mr] = ra[i].w;
            } else {
                int kr = f >> 5, mc = (f & 31) << 2;
                *reinterpret_cast<float4*>(&As[kr][mc]) = ra[i];
            }
        }
    };
    auto stSB = [&]() {
#pragma unroll
        for (int i = 0; i < 2; i++) {
            int f = tid + (i << 8);
            if constexpr (BKF) {
                int nr = f >> 2, kc = (f & 3) << 2;
                Bs[kc + 0][nr] = rb[i].x; Bs[kc + 1][nr] = rb[i].y;
                Bs[kc + 2][nr] = rb[i].z; Bs[kc + 3][nr] = rb[i].w;
            } else {
                int kr = f >> 5, nc = (f & 31) << 2;
                *reinterpret_cast<float4*>(&Bs[kr][nc]) = rb[i];
            }
        }
    };

    const int ntiles = Kloc >> 4;
    ldGA(k0); ldGB(k0);
    stSA();  stSB();
    __syncthreads();

    for (int kt = 0; kt < ntiles; kt++) {
        if (kt + 1 < ntiles) { ldGA(k0 + ((kt + 1) << 4)); ldGB(k0 + ((kt + 1) << 4)); }
#pragma unroll
        for (int kk = 0; kk < 16; kk++) {
            float4 a0 = *reinterpret_cast<const float4*>(&As[kk][ty << 3]);
            float4 a1 = *reinterpret_cast<const float4*>(&As[kk][(ty << 3) + 4]);
            float4 b0 = *reinterpret_cast<const float4*>(&Bs[kk][tx << 3]);
            float4 b1 = *reinterpret_cast<const float4*>(&Bs[kk][(tx << 3) + 4]);
            float av[8] = {a0.x, a0.y, a0.z, a0.w, a1.x, a1.y, a1.z, a1.w};
            float bv[8] = {b0.x, b0.y, b0.z, b0.w, b1.x, b1.y, b1.z, b1.w};
#pragma unroll
            for (int i = 0; i < 8; i++)
#pragma unroll
                for (int j = 0; j < 8; j++)
                    acc[i][j] = fmaf(av[i], bv[j], acc[i][j]);
        }
        __syncthreads();
        if (kt + 1 < ntiles) { stSA(); stSB(); __syncthreads(); }
    }

    float* Cb = Cg + (size_t)blockIdx.z * batC;
    float bc[8];
    if constexpr (EPI == 1) {
#pragma unroll
        for (int j = 0; j < 8; j++) bc[j] = biasC[zb * biasCs + n0 + (tx << 3) + j];
    }
#pragma unroll
    for (int i = 0; i < 8; i++) {
        int r = m0 + (ty << 3) + i;
        float br = 0.f;
        if constexpr (EPI == 1) br = biasR[zb * biasRs + r];
#pragma unroll
        for (int jj = 0; jj < 2; jj++) {
            float4 v;
            v.x = acc[i][jj * 4 + 0]; v.y = acc[i][jj * 4 + 1];
            v.z = acc[i][jj * 4 + 2]; v.w = acc[i][jj * 4 + 3];
            if constexpr (EPI == 1) {
                v.x += br + bc[jj * 4 + 0]; v.y += br + bc[jj * 4 + 1];
                v.z += br + bc[jj * 4 + 2]; v.w += br + bc[jj * 4 + 3];
            }
            *reinterpret_cast<float4*>(Cb + (size_t)r * ldc + n0 + (tx << 3) + (jj << 2)) = v;
        }
    }
}

// ---------------- K3a: softmax over m (rows of S), one warp per row ----------------
__global__ __launch_bounds__(256) void k_softmax_m(const float* __restrict__ qmask) {
    int warp = threadIdx.x >> 5, lane = threadIdx.x & 31;
    int row = blockIdx.x * 8 + warp;      // row = b*LC + l
    int b = row >> 10;                    // LC = 1024
    const float* Sr = g_S + (size_t)row * LQ;
    float v[8];
#pragma unroll
    for (int i = 0; i < 2; i++) {
        int m = i * 128 + lane * 4;
        float4 s  = *reinterpret_cast<const float4*>(Sr + m);
        float4 qm = *reinterpret_cast<const float4*>(qmask + b * LQ + m);
        v[i*4+0] = s.x + (1.f - qm.x) * NEGINF;
        v[i*4+1] = s.y + (1.f - qm.y) * NEGINF;
        v[i*4+2] = s.z + (1.f - qm.z) * NEGINF;
        v[i*4+3] = s.w + (1.f - qm.w) * NEGINF;
    }
    float mx = v[0];
#pragma unroll
    for (int k = 1; k < 8; k++) mx = fmaxf(mx, v[k]);
#pragma unroll
    for (int o = 16; o; o >>= 1) mx = fmaxf(mx, __shfl_xor_sync(0xffffffffu, mx, o));
    float sum = 0.f;
#pragma unroll
    for (int k = 0; k < 8; k++) { v[k] = __expf(v[k] - mx); sum += v[k]; }
#pragma unroll
    for (int o = 16; o; o >>= 1) sum += __shfl_xor_sync(0xffffffffu, sum, o);
    float inv = 1.f / sum;
    float* Or = g_S1 + (size_t)row * LQ;
#pragma unroll
    for (int i = 0; i < 2; i++) {
        int m = i * 128 + lane * 4;
        float4 o;
        o.x = v[i*4+0] * inv; o.y = v[i*4+1] * inv;
        o.z = v[i*4+2] * inv; o.w = v[i*4+3] * inv;
        *reinterpret_cast<float4*>(Or + m) = o;
    }
}

// ---------------- K3b: softmax over l (columns of S), 32 cols per block ----------------
__global__ __launch_bounds__(256) void k_softmax_l(const float* __restrict__ cmask) {
    int b = blockIdx.y;
    int tx = threadIdx.x, ty = threadIdx.y;
    int m = blockIdx.x * 32 + tx;
    const float* Sb = g_S + (size_t)b * LC * LQ + m;
    const float* cm = cmask + b * LC;
    float mx = -3.4e38f, s = 0.f;
    for (int l = ty; l < LC; l += 8) {
        float v = Sb[(size_t)l * LQ] + (1.f - cm[l]) * NEGINF;
        float nm = fmaxf(mx, v);
        s = s * __expf(mx - nm) + __expf(v - nm);
        mx = nm;
    }
    __shared__ float smx[8][33], ssm[8][33];
    smx[ty][tx] = mx; ssm[ty][tx] = s;
    __syncthreads();
    if (ty == 0) {
        float M = smx[0][tx], S = ssm[0][tx];
#pragma unroll
        for (int i = 1; i < 8; i++) {
            float m2 = smx[i][tx], s2 = ssm[i][tx];
            float nm = fmaxf(M, m2);
            S = S * __expf(M - nm) + s2 * __expf(m2 - nm);
            M = nm;
        }
        smx[0][tx] = M; ssm[0][tx] = 1.f / S;
    }
    __syncthreads();
    float M = smx[0][tx], inv = ssm[0][tx];
    float* Ob = g_S2 + (size_t)b * LC * LQ + m;
    for (int l = ty; l < LC; l += 8) {
        float v = Sb[(size_t)l * LQ] + (1.f - cm[l]) * NEGINF;
        Ob[(size_t)l * LQ] = __expf(v - M) * inv;
    }
}

// ---------------- K5b: reduce split-K partials of T ----------------
__global__ void k_reduceT() {
    int idx = blockIdx.x * 256 + threadIdx.x;   // < B_*LQ*D_ = 2097152
    int b = idx >> 15;                          // LQ*D_ = 32768
    int off = idx & 32767;
    size_t base = ((size_t)b * 4) * 32768 + off;
    g_T[idx] = g_Tp[base] + g_Tp[base + 32768] + g_Tp[base + 65536] + g_Tp[base + 98304];
}

// ---------------- K7: assemble output (transpose l<->d, 4 channel groups) ----------------
__global__ __launch_bounds__(256) void k_out(const float* __restrict__ C, float* __restrict__ out) {
    int b = blockIdx.z;
    int lt = blockIdx.x * 32, dt = blockIdx.y * 32;
    int tx = threadIdx.x, ty = threadIdx.y;
    __shared__ float At[32][33], Bt[32][33];
    const float* Ab = g_A  + (size_t)b * LC * D_;
    const float* Vb = g_Bv + (size_t)b * LC * D_;
#pragma unroll
    for (int i = 0; i < 4; i++) {
        int ll = ty + i * 8;
        At[ll][tx] = Ab[(size_t)(lt + ll) * D_ + dt + tx];
        Bt[ll][tx] = Vb[(size_t)(lt + ll) * D_ + dt + tx];
    }
    __syncthreads();
    const float* Cb = C + (size_t)b * D_ * LC;
    float* Ob = out + (size_t)b * 4 * D_ * LC;
#pragma unroll
    for (int j = 0; j < 4; j++) {
        int dl = ty + j * 8;
        int d = dt + dl, l = lt + tx;
        float c = Cb[(size_t)d * LC + l];
        float a = At[tx][dl];
        float v = Bt[tx][dl];
        Ob[(size_t)d * LC + l]            = c;
        Ob[(size_t)(D_ + d) * LC + l]     = a;
        Ob[(size_t)(2 * D_ + d) * LC + l] = c * a;
        Ob[(size_t)(3 * D_ + d) * LC + l] = c * v;
    }
}

// ---------------- launch ----------------
extern "C" void kernel_launch(void* const* d_in, const int* in_sizes, int n_in,
                              void* d_out, int out_size) {
    const float* C     = (const float*)d_in[0];
    const float* Q     = (const float*)d_in[1];
    const float* cmask = (const float*)d_in[2];
    const float* qmask = (const float*)d_in[3];
    const float* w     = (const float*)d_in[4];
    float* out = (float*)d_out;

    float *pS, *pS1, *pS2, *pA, *pBv, *pTp, *pT, *pc1, *pq2;
    cudaGetSymbolAddress((void**)&pS,  g_S);
    cudaGetSymbolAddress((void**)&pS1, g_S1);
    cudaGetSymbolAddress((void**)&pS2, g_S2);
    cudaGetSymbolAddress((void**)&pA,  g_A);
    cudaGetSymbolAddress((void**)&pBv, g_Bv);
    cudaGetSymbolAddress((void**)&pTp, g_Tp);
    cudaGetSymbolAddress((void**)&pT,  g_T);
    cudaGetSymbolAddress((void**)&pc1, g_c1);
    cudaGetSymbolAddress((void**)&pq2, g_q2);

    // K1: bias vectors
    k_bias<<<dim3(5, B_), 256>>>(C, Q, w);

    // K2: S = (C .* w3)^T @ Q + c1 + q2   [M=Lc, N=Lq, K=D]
    gemm128<false, false, true, 1><<<dim3(2, 8, B_), 256>>>(
        C, Q, pS, LC, LQ, LQ, D_, 1,
        (long)D_ * LC, (long)D_ * LQ, (long)LC * LQ,
        w + 2 * D_, pc1, pq2, LC, LQ);

    // K3: softmaxes
    k_softmax_m<<<B_ * LC / 8, 256>>>(qmask);
    k_softmax_l<<<dim3(LQ / 32, B_), dim3(32, 8)>>>(cmask);

    // K4: A = S1 @ Qt   [M=Lc, N=D, K=Lq]
    gemm128<true, true, false, 0><<<dim3(1, 8, B_), 256>>>(
        pS1, Q, pA, LQ, LQ, D_, LQ, 1,
        (long)LC * LQ, (long)D_ * LQ, (long)LC * D_,
        nullptr, nullptr, nullptr, 0, 0);

    // K5: T = S2^T @ Ct   [M=Lq, N=D, K=Lc], deterministic 4-way split-K
    gemm128<false, true, false, 0><<<dim3(1, 2, B_ * 4), 256>>>(
        pS2, C, pTp, LQ, LC, D_, LQ, 4,
        (long)LC * LQ, (long)D_ * LC, (long)LQ * D_,
        nullptr, nullptr, nullptr, 0, 0);
    k_reduceT<<<B_ * LQ * D_ / 256, 256>>>();

    // K6: Bv = S1 @ T   [M=Lc, N=D, K=Lq]
    gemm128<true, false, false, 0><<<dim3(1, 8, B_), 256>>>(
        pS1, pT, pBv, LQ, D_, D_, LQ, 1,
        (long)LC * LQ, (long)LQ * D_, (long)LC * D_,
        nullptr, nullptr, nullptr, 0, 0);

    // K7: output assembly
    k_out<<<dim3(LC / 32, D_ / 32, B_), dim3(32, 8)>>>(C, out);
}

// round 4
// speedup vs baseline: 1.3038x; 1.3038x over previous
#include <cuda_runtime.h>
#include <cuda_bf16.h>
#include <cstdint>

#define B_  64
#define D_  128
#define LC  1024
#define LQ  256
#define LDS_ 40      // smem row stride in bf16 elements (conflict-free for ldmatrix)

// ---------------- scratch (static device arrays) ----------------
static __device__ float g_E  [(size_t)B_*LC*LQ];     // exp(S + biases), unnormalized
static __device__ float g_Cw [(size_t)B_*D_*LC];     // C * w3[d]
static __device__ float g_Ccm[(size_t)B_*D_*LC];     // C * cmask[l]
static __device__ float g_Qm [(size_t)B_*D_*LQ];     // Q * qmask[m]
static __device__ float g_A  [(size_t)B_*LC*D_];     // A matrix  [l][d]
static __device__ float g_Bv [(size_t)B_*LC*D_];     // Bv matrix [l][d]
static __device__ float g_Tp [(size_t)B_*4*LQ*D_];   // split-K partials for T
static __device__ float g_T  [(size_t)B_*LQ*D_];     // T-hat, [m][d]
static __device__ float g_rinv[B_*LC];
static __device__ float g_cinv[B_*LQ];
static __device__ float g_cpart[B_*8*LQ];
static __device__ float g_c1[B_*LC];
static __device__ float g_q2[B_*LQ];

// ---------------- helpers ----------------
__device__ __forceinline__ uint32_t smem_u32(const void* p) {
    uint32_t a;
    asm("{ .reg .u64 t; cvta.to.shared.u64 t, %1; cvt.u32.u64 %0, t; }" : "=r"(a) : "l"(p));
    return a;
}

#define LDSM_X4(r, a) \
    asm volatile("ldmatrix.sync.aligned.m8n8.x4.shared.b16 {%0,%1,%2,%3}, [%4];" \
        : "=r"((r)[0]), "=r"((r)[1]), "=r"((r)[2]), "=r"((r)[3]) : "r"(a))

#define MMA_BF16(c, a, b0, b1) \
    asm volatile("mma.sync.aligned.m16n8k16.row.col.f32.bf16.bf16.f32 " \
        "{%0,%1,%2,%3}, {%4,%5,%6,%7}, {%8,%9}, {%0,%1,%2,%3};" \
        : "+f"((c)[0]), "+f"((c)[1]), "+f"((c)[2]), "+f"((c)[3]) \
        : "r"((a)[0]), "r"((a)[1]), "r"((a)[2]), "r"((a)[3]), "r"(b0), "r"(b1))

// ---------------- bf16 3-pass tensor GEMM: Out(m,n) = sum_k A(m,k)*B(n,k) ----------------
// AT/BT: TRANS flag for each operand. TRANS=false: src[mn*ld + k]; TRANS=true: src[k*ld + mn]
// EPI: 0 plain, 1 exp(acc + biasR[row] + biasC[col]), 2 acc * rscale[row]
template<bool AT, bool BT, int EPI>
__global__ __launch_bounds__(256) void tgemm(
    const float* __restrict__ Ag, int lda, long batA,
    const float* __restrict__ Bg, int ldb, long batB,
    float* __restrict__ Cg, int ldc, long batC,
    int Kloc, int nsplit,
    const float* __restrict__ biasR, const float* __restrict__ biasC,
    const float* __restrict__ rscale)
{
    __shared__ __align__(16) __nv_bfloat16 sAh[128*LDS_], sAl[128*LDS_];
    __shared__ __align__(16) __nv_bfloat16 sBh[128*LDS_], sBl[128*LDS_];

    const int zb = blockIdx.z / nsplit;
    const int sp = blockIdx.z - zb * nsplit;
    const int k0 = sp * Kloc;
    const int m0 = blockIdx.y << 7;
    const int n0 = blockIdx.x << 7;
    const float* Ab = Ag + (size_t)zb * batA;
    const float* Bb = Bg + (size_t)zb * batB;

    const int tid = threadIdx.x, wid = tid >> 5, lane = tid & 31;
    const int wm = (wid >> 2) * 64, wn = (wid & 3) * 32;

    float acc[4][4][4];
#pragma unroll
    for (int i = 0; i < 4; i++)
#pragma unroll
        for (int j = 0; j < 4; j++)
#pragma unroll
            for (int e = 0; e < 4; e++) acc[i][j][e] = 0.f;

    float4 ra[4], rb[4];

    auto ldg = [&](const float* __restrict__ src, int ld, int mn0, int kk,
                   bool trans, float4 (&r)[4]) {
        if (!trans) {
#pragma unroll
            for (int i = 0; i < 4; i++) {
                int v = i * 256 + tid;
                int row = v >> 3, c4 = v & 7;
                r[i] = *reinterpret_cast<const float4*>(src + (size_t)(mn0 + row) * ld + kk + c4 * 4);
            }
        } else {
#pragma unroll
            for (int i = 0; i < 4; i++) {
                int v = i * 256 + tid;
                int kr = v >> 5, c4 = v & 31;
                r[i] = *reinterpret_cast<const float4*>(src + (size_t)(kk + kr) * ld + mn0 + c4 * 4);
            }
        }
    };

    auto sts = [&](float4 (&r)[4], __nv_bfloat16* smh, __nv_bfloat16* sml, bool trans) {
#pragma unroll
        for (int i = 0; i < 4; i++) {
            float vv[4] = {r[i].x, r[i].y, r[i].z, r[i].w};
            __nv_bfloat16 hv[4];
            float lv[4];
#pragma unroll
            for (int e = 0; e < 4; e++) {
                hv[e] = __float2bfloat16(vv[e]);
                lv[e] = vv[e] - __bfloat162float(hv[e]);
            }
            if (!trans) {
                int v = i * 256 + tid;
                int row = v >> 3, c4 = v & 7;
                int off = row * LDS_ + c4 * 4;
                __nv_bfloat162 h0; h0.x = hv[0]; h0.y = hv[1];
                __nv_bfloat162 h1; h1.x = hv[2]; h1.y = hv[3];
                *reinterpret_cast<__nv_bfloat162*>(smh + off)     = h0;
                *reinterpret_cast<__nv_bfloat162*>(smh + off + 2) = h1;
                __nv_bfloat162 l0; l0.x = __float2bfloat16(lv[0]); l0.y = __float2bfloat16(lv[1]);
                __nv_bfloat162 l1; l1.x = __float2bfloat16(lv[2]); l1.y = __float2bfloat16(lv[3]);
                *reinterpret_cast<__nv_bfloat162*>(sml + off)     = l0;
                *reinterpret_cast<__nv_bfloat162*>(sml + off + 2) = l1;
            } else {
                int v = i * 256 + tid;
                int kr = v >> 5, c4 = v & 31;
#pragma unroll
                for (int e = 0; e < 4; e++) {
                    int off = (c4 * 4 + e) * LDS_ + kr;
                    smh[off] = hv[e];
                    sml[off] = __float2bfloat16(lv[e]);
                }
            }
        }
    };

    const uint32_t bAh = smem_u32(sAh), bAl = smem_u32(sAl);
    const uint32_t bBh = smem_u32(sBh), bBl = smem_u32(sBl);

    const int nch = Kloc >> 5;
    ldg(Ab, lda, m0, k0, AT, ra);
    ldg(Bb, ldb, n0, k0, BT, rb);

    for (int ch = 0; ch < nch; ch++) {
        sts(ra, sAh, sAl, AT);
        sts(rb, sBh, sBl, BT);
        __syncthreads();
        if (ch + 1 < nch) {
            int kk = k0 + ((ch + 1) << 5);
            ldg(Ab, lda, m0, kk, AT, ra);
            ldg(Bb, ldb, n0, kk, BT, rb);
        }
#pragma unroll
        for (int ks = 0; ks < 2; ks++) {
            uint32_t afh[4][4], afl[4][4];
#pragma unroll
            for (int mt = 0; mt < 4; mt++) {
                uint32_t aoff = (uint32_t)((wm + mt * 16 + (lane & 15)) * LDS_
                                           + ks * 16 + ((lane >> 4) << 3)) * 2u;
                LDSM_X4(afh[mt], bAh + aoff);
                LDSM_X4(afl[mt], bAl + aoff);
            }
            uint32_t bfh[2][4], bfl[2][4];
#pragma unroll
            for (int nt = 0; nt < 2; nt++) {
                uint32_t boff = (uint32_t)((wn + nt * 16 + ((lane >> 4) << 3) + (lane & 7)) * LDS_
                                           + ks * 16 + (((lane >> 3) & 1) << 3)) * 2u;
                LDSM_X4(bfh[nt], bBh + boff);
                LDSM_X4(bfl[nt], bBl + boff);
            }
#pragma unroll
            for (int mt = 0; mt < 4; mt++)
#pragma unroll
                for (int nt = 0; nt < 2; nt++)
#pragma unroll
                    for (int h = 0; h < 2; h++) {
                        float* c = acc[mt][nt * 2 + h];
                        MMA_BF16(c, afh[mt], bfh[nt][2 * h], bfh[nt][2 * h + 1]);
                        MMA_BF16(c, afh[mt], bfl[nt][2 * h], bfl[nt][2 * h + 1]);
                        MMA_BF16(c, afl[mt], bfh[nt][2 * h], bfh[nt][2 * h + 1]);
                    }
        }
        __syncthreads();
    }

    // epilogue
    float* Cb = Cg + (size_t)blockIdx.z * batC;
#pragma unroll
    for (int mt = 0; mt < 4; mt++) {
        int r0 = m0 + wm + mt * 16 + (lane >> 2);
        int r1 = r0 + 8;
        float s0 = 1.f, s1 = 1.f, br0 = 0.f, br1 = 0.f;
        if constexpr (EPI == 2) { s0 = rscale[zb * LC + r0]; s1 = rscale[zb * LC + r1]; }
        if constexpr (EPI == 1) { br0 = biasR[zb * LC + r0]; br1 = biasR[zb * LC + r1]; }
#pragma unroll
        for (int nt = 0; nt < 4; nt++) {
            int col = n0 + wn + nt * 8 + (lane & 3) * 2;
            float2 v0, v1;
            v0.x = acc[mt][nt][0]; v0.y = acc[mt][nt][1];
            v1.x = acc[mt][nt][2]; v1.y = acc[mt][nt][3];
            if constexpr (EPI == 1) {
                float bc0 = biasC[zb * LQ + col], bc1 = biasC[zb * LQ + col + 1];
                v0.x = __expf(v0.x + br0 + bc0); v0.y = __expf(v0.y + br0 + bc1);
                v1.x = __expf(v1.x + br1 + bc0); v1.y = __expf(v1.y + br1 + bc1);
            }
            if constexpr (EPI == 2) {
                v0.x *= s0; v0.y *= s0; v1.x *= s1; v1.y *= s1;
            }
            *reinterpret_cast<float2*>(Cb + (size_t)r0 * ldc + col) = v0;
            *reinterpret_cast<float2*>(Cb + (size_t)r1 * ldc + col) = v1;
        }
    }
}

// ---------------- K1: bias vectors c1[l] = Ct.w1, q2[m] = Qt.w2 ----------------
__global__ void k_bias(const float* __restrict__ C, const float* __restrict__ Q,
                       const float* __restrict__ w) {
    int b = blockIdx.y, seg = blockIdx.x, t = threadIdx.x;
    if (seg < 4) {
        int l = seg * 256 + t;
        const float* Cb = C + (size_t)b * D_ * LC;
        float acc = 0.f;
#pragma unroll 8
        for (int d = 0; d < D_; d++) acc += Cb[(size_t)d * LC + l] * __ldg(w + d);
        g_c1[b * LC + l] = acc;
    } else {
        int m = t;
        const float* Qb = Q + (size_t)b * D_ * LQ;
        float acc = 0.f;
#pragma unroll 8
        for (int d = 0; d < D_; d++) acc += Qb[(size_t)d * LQ + m] * __ldg(w + D_ + d);
        g_q2[b * LQ + m] = acc;
    }
}

// ---------------- prep: Cw = C*w3[d], Ccm = C*cmask[l], Qm = Q*qmask[m] ----------------
__global__ __launch_bounds__(256) void k_prep(const float* __restrict__ C, const float* __restrict__ Q,
                                              const float* __restrict__ w,
                                              const float* __restrict__ cmask,
                                              const float* __restrict__ qmask) {
    int idx = blockIdx.x * 256 + threadIdx.x;          // over B*D*LC = 8388608
    int b = idx >> 17;                                  // D*LC = 131072
    int r = idx & 131071;
    int d = r >> 10, l = r & 1023;
    float c = C[idx];
    g_Cw[idx]  = c * __ldg(w + 2 * D_ + d);
    g_Ccm[idx] = c * cmask[b * LC + l];
    if (idx < B_ * D_ * LQ) {
        int b2 = idx >> 15;                             // D*LQ = 32768
        int m = idx & 255;
        g_Qm[idx] = Q[idx] * qmask[b2 * LQ + m];
    }
}

// ---------------- sums: rinv[l] = 1/sum_m E*qm, col partials for cinv ----------------
__global__ __launch_bounds__(256) void k_sums(const float* __restrict__ qmask,
                                              const float* __restrict__ cmask) {
    int b = blockIdx.y, rc = blockIdx.x;
    int w = threadIdx.x >> 5, lane = threadIdx.x & 31;
    __shared__ float cp[8][256];
    float4 q0 = *reinterpret_cast<const float4*>(qmask + b * LQ + lane * 4);
    float4 q1 = *reinterpret_cast<const float4*>(qmask + b * LQ + 128 + lane * 4);
    float col[8] = {0.f, 0.f, 0.f, 0.f, 0.f, 0.f, 0.f, 0.f};
#pragma unroll 4
    for (int rr = 0; rr < 16; rr++) {
        int l = rc * 128 + w * 16 + rr;
        const float* Er = g_E + ((size_t)b * LC + l) * LQ;
        float4 e0 = *reinterpret_cast<const float4*>(Er + lane * 4);
        float4 e1 = *reinterpret_cast<const float4*>(Er + 128 + lane * 4);
        float cm = cmask[b * LC + l];
        col[0] += e0.x * cm; col[1] += e0.y * cm; col[2] += e0.z * cm; col[3] += e0.w * cm;
        col[4] += e1.x * cm; col[5] += e1.y * cm; col[6] += e1.z * cm; col[7] += e1.w * cm;
        float s = e0.x * q0.x + e0.y * q0.y + e0.z * q0.z + e0.w * q0.w
                + e1.x * q1.x + e1.y * q1.y + e1.z * q1.z + e1.w * q1.w;
#pragma unroll
        for (int o = 16; o; o >>= 1) s += __shfl_xor_sync(0xffffffffu, s, o);
        if (lane == 0) g_rinv[b * LC + l] = 1.f / s;
    }
#pragma unroll
    for (int j = 0; j < 4; j++) {
        cp[w][lane * 4 + j] = col[j];
        cp[w][128 + lane * 4 + j] = col[4 + j];
    }
    __syncthreads();
    int m = threadIdx.x;
    float c = cp[0][m] + cp[1][m] + cp[2][m] + cp[3][m]
            + cp[4][m] + cp[5][m] + cp[6][m] + cp[7][m];
    g_cpart[(b * 8 + rc) * 256 + m] = c;
}

__global__ void k_colfin() {
    int b = blockIdx.x, m = threadIdx.x;
    const float* p = g_cpart + b * 8 * 256 + m;
    float c = p[0] + p[256] + p[512] + p[768] + p[1024] + p[1280] + p[1536] + p[1792];
    g_cinv[b * LQ + m] = 1.f / c;
}

// ---------------- reduce T partials, apply qm(m)*cinv(m) ----------------
__global__ void k_redT(const float* __restrict__ qmask) {
    int idx = blockIdx.x * 256 + threadIdx.x;      // < B*LQ*D = 2097152
    int b = idx >> 15;                             // LQ*D = 32768
    int off = idx & 32767;
    int m = off >> 7;
    size_t base = ((size_t)b * 4) * 32768 + off;
    float v = g_Tp[base] + g_Tp[base + 32768] + g_Tp[base + 65536] + g_Tp[base + 98304];
    g_T[idx] = v * qmask[b * LQ + m] * g_cinv[b * LQ + m];
}

// ---------------- output assembly (transpose l<->d, 4 channel groups) ----------------
__global__ __launch_bounds__(256) void k_out(const float* __restrict__ C, float* __restrict__ out) {
    int b = blockIdx.z;
    int lt = blockIdx.x * 32, dt = blockIdx.y * 32;
    int tx = threadIdx.x, ty = threadIdx.y;
    __shared__ float At[32][33], Bt[32][33];
    const float* Ab = g_A  + (size_t)b * LC * D_;
    const float* Vb = g_Bv + (size_t)b * LC * D_;
#pragma unroll
    for (int i = 0; i < 4; i++) {
        int ll = ty + i * 8;
        At[ll][tx] = Ab[(size_t)(lt + ll) * D_ + dt + tx];
        Bt[ll][tx] = Vb[(size_t)(lt + ll) * D_ + dt + tx];
    }
    __syncthreads();
    const float* Cb = C + (size_t)b * D_ * LC;
    float* Ob = out + (size_t)b * 4 * D_ * LC;
#pragma unroll
    for (int j = 0; j < 4; j++) {
        int dl = ty + j * 8;
        int d = dt + dl, l = lt + tx;
        float c = Cb[(size_t)d * LC + l];
        float a = At[tx][dl];
        float v = Bt[tx][dl];
        Ob[(size_t)d * LC + l]            = c;
        Ob[(size_t)(D_ + d) * LC + l]     = a;
        Ob[(size_t)(2 * D_ + d) * LC + l] = c * a;
        Ob[(size_t)(3 * D_ + d) * LC + l] = c * v;
    }
}

// ---------------- launch ----------------
extern "C" void kernel_launch(void* const* d_in, const int* in_sizes, int n_in,
                              void* d_out, int out_size) {
    const float* C     = (const float*)d_in[0];
    const float* Q     = (const float*)d_in[1];
    const float* cmask = (const float*)d_in[2];
    const float* qmask = (const float*)d_in[3];
    const float* w     = (const float*)d_in[4];
    float* out = (float*)d_out;

    float *pE, *pCw, *pCcm, *pQm, *pA, *pBv, *pTp, *pT, *pc1, *pq2, *prv;
    cudaGetSymbolAddress((void**)&pE,   g_E);
    cudaGetSymbolAddress((void**)&pCw,  g_Cw);
    cudaGetSymbolAddress((void**)&pCcm, g_Ccm);
    cudaGetSymbolAddress((void**)&pQm,  g_Qm);
    cudaGetSymbolAddress((void**)&pA,   g_A);
    cudaGetSymbolAddress((void**)&pBv,  g_Bv);
    cudaGetSymbolAddress((void**)&pTp,  g_Tp);
    cudaGetSymbolAddress((void**)&pT,   g_T);
    cudaGetSymbolAddress((void**)&pc1,  g_c1);
    cudaGetSymbolAddress((void**)&pq2,  g_q2);
    cudaGetSymbolAddress((void**)&prv,  g_rinv);

    // K1: bias vectors
    k_bias<<<dim3(5, B_), 256>>>(C, Q, w);
    // prep scaled copies
    k_prep<<<B_ * D_ * LC / 256, 256>>>(C, Q, w, cmask, qmask);

    // G1: E = exp((Cw)^T Q + c1 + q2)   [M=Lc, N=Lq, K=D]; both operands MN-major
    tgemm<true, true, 1><<<dim3(2, 8, B_), 256>>>(
        pCw, LC, (long)D_ * LC,  Q, LQ, (long)D_ * LQ,
        pE, LQ, (long)LC * LQ,  D_, 1,  pc1, pq2, nullptr);

    // sums: rinv, colsum partials -> cinv
    k_sums<<<dim3(8, B_), 256>>>(qmask, cmask);
    k_colfin<<<B_, 256>>>();

    // G2: A = (E @ Qm^T) * rinv[row]   [M=Lc, N=D, K=Lq]
    tgemm<false, false, 2><<<dim3(1, 8, B_), 256>>>(
        pE, LQ, (long)LC * LQ,  pQm, LQ, (long)D_ * LQ,
        pA, D_, (long)LC * D_,  LQ, 1,  nullptr, nullptr, prv);

    // G3: Tp = E^T @ Ccm^T  (split-K 4)   [M=Lq, N=D, K=Lc]; A MN-major
    tgemm<true, false, 0><<<dim3(1, 2, B_ * 4), 256>>>(
        pE, LQ, (long)LC * LQ,  pCcm, LC, (long)D_ * LC,
        pTp, D_, (long)LQ * D_,  LQ, 4,  nullptr, nullptr, nullptr);
    k_redT<<<B_ * LQ * D_ / 256, 256>>>(qmask);

    // G4: Bv = (E @ That) * rinv[row]   [M=Lc, N=D, K=Lq]; B (That) MN-major
    tgemm<false, true, 2><<<dim3(1, 8, B_), 256>>>(
        pE, LQ, (long)LC * LQ,  pT, D_, (long)LQ * D_,
        pBv, D_, (long)LC * D_,  LQ, 1,  nullptr, nullptr, prv);

    // output assembly
    k_out<<<dim3(LC / 32, D_ / 32, B_), dim3(32, 8)>>>(C, out);
}

// round 5
// speedup vs baseline: 2.1597x; 1.6564x over previous
#include <cuda_runtime.h>
#include <cuda_bf16.h>
#include <cstdint>

#define B_  64
#define D_  128
#define LC  1024
#define LQ  256
#define LDS_ 40      // smem row stride in bf16 elements (conflict-free for ldmatrix)

// ---------------- scratch (static device arrays) ----------------
static __device__ float g_E   [(size_t)B_*LC*LQ];    // exp(S + biases), unnormalized
static __device__ float g_At  [(size_t)B_*D_*LC];    // A^T  [d][l]
static __device__ float g_Bvt [(size_t)B_*D_*LC];    // Bv^T [d][l]
static __device__ float g_T   [(size_t)B_*LQ*D_];    // T-hat [m][d] (qm*cinv folded)
static __device__ float g_rinv[B_*LC];
static __device__ float g_qcinv[B_*LQ];
static __device__ float g_cpart[B_*8*LQ];
static __device__ float g_c1[B_*LC];
static __device__ float g_q2[B_*LQ];

// ---------------- helpers ----------------
__device__ __forceinline__ uint32_t smem_u32(const void* p) {
    uint32_t a;
    asm("{ .reg .u64 t; cvta.to.shared.u64 t, %1; cvt.u32.u64 %0, t; }" : "=r"(a) : "l"(p));
    return a;
}

#define LDSM_X4(r, a) \
    asm volatile("ldmatrix.sync.aligned.m8n8.x4.shared.b16 {%0,%1,%2,%3}, [%4];" \
        : "=r"((r)[0]), "=r"((r)[1]), "=r"((r)[2]), "=r"((r)[3]) : "r"(a))

#define MMA_BF16(c, a, b0, b1) \
    asm volatile("mma.sync.aligned.m16n8k16.row.col.f32.bf16.bf16.f32 " \
        "{%0,%1,%2,%3}, {%4,%5,%6,%7}, {%8,%9}, {%0,%1,%2,%3};" \
        : "+f"((c)[0]), "+f"((c)[1]), "+f"((c)[2]), "+f"((c)[3]) \
        : "r"((a)[0]), "r"((a)[1]), "r"((a)[2]), "r"((a)[3]), "r"(b0), "r"(b1))

// ---------------- operand loaders ----------------
// logical layout in smem: element (mn, klocal) at smem[mn*LDS_ + klocal], klocal in [0,32)
// TRANS=false: src element (mn, k) at src[mn*ld + k]  (K contiguous)
// TRANS=true : src element (mn, k) at src[k*ld + mn]  (MN contiguous) -> load along K
template<bool TRANS, bool KS>
__device__ __forceinline__ void ldg_op(const float* __restrict__ src, int ld, int mn0,
                                       int kk, const float* __restrict__ ks,
                                       int tid, float4 (&r)[4]) {
#pragma unroll
    for (int i = 0; i < 4; i++) {
        int v = i * 256 + tid;
        if constexpr (!TRANS) {
            int row = v >> 3, c4 = v & 7;
            float4 x = *reinterpret_cast<const float4*>(src + (size_t)(mn0 + row) * ld + kk + c4 * 4);
            if constexpr (KS) {
                float4 s = *reinterpret_cast<const float4*>(ks + kk + c4 * 4);
                x.x *= s.x; x.y *= s.y; x.z *= s.z; x.w *= s.w;
            }
            r[i] = x;
        } else {
            int mn = v & 127, krb = v >> 7;          // krb in [0,8): k = krb*4..+3
            const float* p = src + (size_t)(kk + krb * 4) * ld + mn0 + mn;
            float4 x;
            x.x = p[0]; x.y = p[ld]; x.z = p[2 * (size_t)ld]; x.w = p[3 * (size_t)ld];
            if constexpr (KS) {
                const float* s = ks + kk + krb * 4;
                x.x *= s[0]; x.y *= s[1]; x.z *= s[2]; x.w *= s[3];
            }
            r[i] = x;
        }
    }
}

template<bool TRANS>
__device__ __forceinline__ void sts_op(float4 (&r)[4], __nv_bfloat16* smh, __nv_bfloat16* sml, int tid) {
#pragma unroll
    for (int i = 0; i < 4; i++) {
        float vv[4] = {r[i].x, r[i].y, r[i].z, r[i].w};
        __nv_bfloat16 hv[4], lv[4];
#pragma unroll
        for (int e = 0; e < 4; e++) {
            hv[e] = __float2bfloat16(vv[e]);
            lv[e] = __float2bfloat16(vv[e] - __bfloat162float(hv[e]));
        }
        int v = i * 256 + tid;
        int off;
        if constexpr (!TRANS) { int row = v >> 3, c4 = v & 7; off = row * LDS_ + c4 * 4; }
        else                  { int mn = v & 127, krb = v >> 7; off = mn * LDS_ + krb * 4; }
        __nv_bfloat162 h01(hv[0], hv[1]), h23(hv[2], hv[3]);
        __nv_bfloat162 l01(lv[0], lv[1]), l23(lv[2], lv[3]);
        uint2 uh, ul;
        uh.x = *reinterpret_cast<uint32_t*>(&h01); uh.y = *reinterpret_cast<uint32_t*>(&h23);
        ul.x = *reinterpret_cast<uint32_t*>(&l01); ul.y = *reinterpret_cast<uint32_t*>(&l23);
        *reinterpret_cast<uint2*>(smh + off) = uh;
        *reinterpret_cast<uint2*>(sml + off) = ul;
    }
}

// ---------------- bf16 3-pass tensor GEMM: Out(m,n) = sum_k A(m,k)*B(n,k) ----------------
// EPI: 1 = exp(acc + c1[row] + q2[col]) ; 2 = acc * scale[row] ; 3 = acc * scale[col]
template<bool AT, bool BT, bool KSA, bool KSB, int EPI>
__global__ __launch_bounds__(256) void tgemm(
    const float* __restrict__ Ag, int lda, long batA,
    const float* __restrict__ Bg, int ldb, long batB,
    float* __restrict__ Cg, int ldc, long batC,
    int Kloc,
    const float* __restrict__ ksA, int ksAstr,
    const float* __restrict__ ksB, int ksBstr,
    const float* __restrict__ biasR, const float* __restrict__ biasC,
    const float* __restrict__ scale, int scaleStr)
{
    __shared__ __align__(16) __nv_bfloat16 sAh[128*LDS_], sAl[128*LDS_];
    __shared__ __align__(16) __nv_bfloat16 sBh[128*LDS_], sBl[128*LDS_];

    const int zb = blockIdx.z;
    const int m0 = blockIdx.y << 7;
    const int n0 = blockIdx.x << 7;
    const float* Ab = Ag + (size_t)zb * batA;
    const float* Bb = Bg + (size_t)zb * batB;
    const float* kA = KSA ? (ksA + (size_t)zb * ksAstr) : nullptr;
    const float* kB = KSB ? (ksB + (size_t)zb * ksBstr) : nullptr;

    const int tid = threadIdx.x, wid = tid >> 5, lane = tid & 31;
    const int wm = (wid >> 2) * 64, wn = (wid & 3) * 32;

    float acc[4][4][4];
#pragma unroll
    for (int i = 0; i < 4; i++)
#pragma unroll
        for (int j = 0; j < 4; j++)
#pragma unroll
            for (int e = 0; e < 4; e++) acc[i][j][e] = 0.f;

    float4 ra[4], rb[4];
    const uint32_t bAh = smem_u32(sAh), bAl = smem_u32(sAl);
    const uint32_t bBh = smem_u32(sBh), bBl = smem_u32(sBl);

    const int nch = Kloc >> 5;
    ldg_op<AT, KSA>(Ab, lda, m0, 0, kA, tid, ra);
    ldg_op<BT, KSB>(Bb, ldb, n0, 0, kB, tid, rb);

    for (int ch = 0; ch < nch; ch++) {
        sts_op<AT>(ra, sAh, sAl, tid);
        sts_op<BT>(rb, sBh, sBl, tid);
        __syncthreads();
        if (ch + 1 < nch) {
            int kk = (ch + 1) << 5;
            ldg_op<AT, KSA>(Ab, lda, m0, kk, kA, tid, ra);
            ldg_op<BT, KSB>(Bb, ldb, n0, kk, kB, tid, rb);
        }
#pragma unroll
        for (int ks = 0; ks < 2; ks++) {
            uint32_t afh[4][4], afl[4][4];
#pragma unroll
            for (int mt = 0; mt < 4; mt++) {
                uint32_t aoff = (uint32_t)((wm + mt * 16 + (lane & 15)) * LDS_
                                           + ks * 16 + ((lane >> 4) << 3)) * 2u;
                LDSM_X4(afh[mt], bAh + aoff);
                LDSM_X4(afl[mt], bAl + aoff);
            }
            uint32_t bfh[2][4], bfl[2][4];
#pragma unroll
            for (int nt = 0; nt < 2; nt++) {
                uint32_t boff = (uint32_t)((wn + nt * 16 + ((lane >> 4) << 3) + (lane & 7)) * LDS_
                                           + ks * 16 + (((lane >> 3) & 1) << 3)) * 2u;
                LDSM_X4(bfh[nt], bBh + boff);
                LDSM_X4(bfl[nt], bBl + boff);
            }
#pragma unroll
            for (int mt = 0; mt < 4; mt++)
#pragma unroll
                for (int nt = 0; nt < 2; nt++)
#pragma unroll
                    for (int h = 0; h < 2; h++) {
                        float* c = acc[mt][nt * 2 + h];
                        MMA_BF16(c, afh[mt], bfh[nt][2 * h], bfh[nt][2 * h + 1]);
                        MMA_BF16(c, afh[mt], bfl[nt][2 * h], bfl[nt][2 * h + 1]);
                        MMA_BF16(c, afl[mt], bfh[nt][2 * h], bfh[nt][2 * h + 1]);
                    }
        }
        __syncthreads();
    }

    // epilogue
    float* Cb = Cg + (size_t)zb * batC;
#pragma unroll
    for (int mt = 0; mt < 4; mt++) {
        int r0 = m0 + wm + mt * 16 + (lane >> 2);
        int r1 = r0 + 8;
        float s0 = 1.f, s1 = 1.f, br0 = 0.f, br1 = 0.f;
        if constexpr (EPI == 2) { s0 = scale[zb * scaleStr + r0]; s1 = scale[zb * scaleStr + r1]; }
        if constexpr (EPI == 1) { br0 = biasR[zb * LC + r0]; br1 = biasR[zb * LC + r1]; }
#pragma unroll
        for (int nt = 0; nt < 4; nt++) {
            int col = n0 + wn + nt * 8 + (lane & 3) * 2;
            float2 v0, v1;
            v0.x = acc[mt][nt][0]; v0.y = acc[mt][nt][1];
            v1.x = acc[mt][nt][2]; v1.y = acc[mt][nt][3];
            if constexpr (EPI == 1) {
                float bc0 = biasC[zb * LQ + col], bc1 = biasC[zb * LQ + col + 1];
                v0.x = __expf(v0.x + br0 + bc0); v0.y = __expf(v0.y + br0 + bc1);
                v1.x = __expf(v1.x + br1 + bc0); v1.y = __expf(v1.y + br1 + bc1);
            }
            if constexpr (EPI == 2) {
                v0.x *= s0; v0.y *= s0; v1.x *= s1; v1.y *= s1;
            }
            if constexpr (EPI == 3) {
                float c0 = scale[zb * scaleStr + col], c1v = scale[zb * scaleStr + col + 1];
                v0.x *= c0; v0.y *= c1v; v1.x *= c0; v1.y *= c1v;
            }
            *reinterpret_cast<float2*>(Cb + (size_t)r0 * ldc + col) = v0;
            *reinterpret_cast<float2*>(Cb + (size_t)r1 * ldc + col) = v1;
        }
    }
}

// ---------------- K1: bias vectors c1[l] = Ct.w1, q2[m] = Qt.w2 ----------------
__global__ void k_bias(const float* __restrict__ C, const float* __restrict__ Q,
                       const float* __restrict__ w) {
    int b = blockIdx.y, seg = blockIdx.x, t = threadIdx.x;
    if (seg < 4) {
        int l = seg * 256 + t;
        const float* Cb = C + (size_t)b * D_ * LC;
        float acc = 0.f;
#pragma unroll 8
        for (int d = 0; d < D_; d++) acc += Cb[(size_t)d * LC + l] * __ldg(w + d);
        g_c1[b * LC + l] = acc;
    } else {
        int m = t;
        const float* Qb = Q + (size_t)b * D_ * LQ;
        float acc = 0.f;
#pragma unroll 8
        for (int d = 0; d < D_; d++) acc += Qb[(size_t)d * LQ + m] * __ldg(w + D_ + d);
        g_q2[b * LQ + m] = acc;
    }
}

// ---------------- sums: rinv[l] = 1/sum_m E*qm, col partials for cinv ----------------
__global__ __launch_bounds__(256) void k_sums(const float* __restrict__ qmask,
                                              const float* __restrict__ cmask) {
    int b = blockIdx.y, rc = blockIdx.x;
    int w = threadIdx.x >> 5, lane = threadIdx.x & 31;
    __shared__ float cp[8][256];
    float4 q0 = *reinterpret_cast<const float4*>(qmask + b * LQ + lane * 4);
    float4 q1 = *reinterpret_cast<const float4*>(qmask + b * LQ + 128 + lane * 4);
    float col[8] = {0.f, 0.f, 0.f, 0.f, 0.f, 0.f, 0.f, 0.f};
#pragma unroll 4
    for (int rr = 0; rr < 16; rr++) {
        int l = rc * 128 + w * 16 + rr;
        const float* Er = g_E + ((size_t)b * LC + l) * LQ;
        float4 e0 = *reinterpret_cast<const float4*>(Er + lane * 4);
        float4 e1 = *reinterpret_cast<const float4*>(Er + 128 + lane * 4);
        float cm = cmask[b * LC + l];
        col[0] += e0.x * cm; col[1] += e0.y * cm; col[2] += e0.z * cm; col[3] += e0.w * cm;
        col[4] += e1.x * cm; col[5] += e1.y * cm; col[6] += e1.z * cm; col[7] += e1.w * cm;
        float s = e0.x * q0.x + e0.y * q0.y + e0.z * q0.z + e0.w * q0.w
                + e1.x * q1.x + e1.y * q1.y + e1.z * q1.z + e1.w * q1.w;
#pragma unroll
        for (int o = 16; o; o >>= 1) s += __shfl_xor_sync(0xffffffffu, s, o);
        if (lane == 0) g_rinv[b * LC + l] = 1.f / s;
    }
#pragma unroll
    for (int j = 0; j < 4; j++) {
        cp[w][lane * 4 + j] = col[j];
        cp[w][128 + lane * 4 + j] = col[4 + j];
    }
    __syncthreads();
    int m = threadIdx.x;
    float c = cp[0][m] + cp[1][m] + cp[2][m] + cp[3][m]
            + cp[4][m] + cp[5][m] + cp[6][m] + cp[7][m];
    g_cpart[(b * 8 + rc) * 256 + m] = c;
}

__global__ void k_colfin(const float* __restrict__ qmask) {
    int b = blockIdx.x, m = threadIdx.x;
    const float* p = g_cpart + b * 8 * 256 + m;
    float c = p[0] + p[256] + p[512] + p[768] + p[1024] + p[1280] + p[1536] + p[1792];
    g_qcinv[b * LQ + m] = qmask[b * LQ + m] / c;
}

// ---------------- output assembly: pure streaming (A^T, Bv^T already [d][l]) ----------------
__global__ __launch_bounds__(256) void k_out(const float* __restrict__ C, float* __restrict__ out) {
    int i4 = blockIdx.x * 256 + threadIdx.x;        // float4 index over B*D*LC/4
    size_t base = (size_t)i4 * 4;
    int b = i4 >> 15;                               // D*LC/4 = 32768 float4 per batch
    size_t r = base - (size_t)b * D_ * LC;
    float4 c = *reinterpret_cast<const float4*>(C + base);
    float4 a = *reinterpret_cast<const float4*>(g_At + base);
    float4 v = *reinterpret_cast<const float4*>(g_Bvt + base);
    float* Ob = out + (size_t)b * 4 * D_ * LC;
    float4 ca, cv;
    ca.x = c.x * a.x; ca.y = c.y * a.y; ca.z = c.z * a.z; ca.w = c.w * a.w;
    cv.x = c.x * v.x; cv.y = c.y * v.y; cv.z = c.z * v.z; cv.w = c.w * v.w;
    *reinterpret_cast<float4*>(Ob + r)                      = c;
    *reinterpret_cast<float4*>(Ob + (size_t)D_ * LC + r)    = a;
    *reinterpret_cast<float4*>(Ob + (size_t)2 * D_ * LC + r) = ca;
    *reinterpret_cast<float4*>(Ob + (size_t)3 * D_ * LC + r) = cv;
}

// ---------------- launch ----------------
extern "C" void kernel_launch(void* const* d_in, const int* in_sizes, int n_in,
                              void* d_out, int out_size) {
    const float* C     = (const float*)d_in[0];
    const float* Q     = (const float*)d_in[1];
    const float* cmask = (const float*)d_in[2];
    const float* qmask = (const float*)d_in[3];
    const float* w     = (const float*)d_in[4];
    float* out = (float*)d_out;

    float *pE, *pAt, *pBvt, *pT, *pc1, *pq2, *prv, *pqc;
    cudaGetSymbolAddress((void**)&pE,   g_E);
    cudaGetSymbolAddress((void**)&pAt,  g_At);
    cudaGetSymbolAddress((void**)&pBvt, g_Bvt);
    cudaGetSymbolAddress((void**)&pT,   g_T);
    cudaGetSymbolAddress((void**)&pc1,  g_c1);
    cudaGetSymbolAddress((void**)&pq2,  g_q2);
    cudaGetSymbolAddress((void**)&prv,  g_rinv);
    cudaGetSymbolAddress((void**)&pqc,  g_qcinv);

    // K1: bias vectors
    k_bias<<<dim3(5, B_), 256>>>(C, Q, w);

    // G1: E = exp((C*w3)^T Q + c1 + q2)  [m=l (8 tiles), n=m' (2 tiles), K=D]
    // A = C, AT (k=d slow), kscale = w3 (batch stride 0); B = Q, BT (k=d slow)
    tgemm<true, true, true, false, 1><<<dim3(2, 8, B_), 256>>>(
        C, LC, (long)D_ * LC,  Q, LQ, (long)D_ * LQ,
        pE, LQ, (long)LC * LQ,  D_,
        w + 2 * D_, 0,  nullptr, 0,  pc1, pq2,  nullptr, 0);

    // sums -> rinv, col partials -> qcinv
    k_sums<<<dim3(8, B_), 256>>>(qmask, cmask);
    k_colfin<<<B_, 256>>>(qmask);

    // G3: T[m'][d] = (sum_l E(l,m')*cm(l)*C(d,l)) * qm(m')*cinv(m')   [m=m' (2 tiles), n=d (1 tile), K=Lc]
    // A = E^T (AT, ld LQ); B = C (k=l fast, ld LC, kscale cmask); EPI=2 scale rows by qcinv
    tgemm<true, false, false, true, 2><<<dim3(1, 2, B_), 256>>>(
        pE, LQ, (long)LC * LQ,  C, LC, (long)D_ * LC,
        pT, D_, (long)LQ * D_,  LC,
        nullptr, 0,  cmask, LC,  nullptr, nullptr,  pqc, LQ);

    // G2: A^T[d][l] = (sum_m' Q(d,m')*qm(m')*E(l,m')) * rinv(l)   [m=d (1 tile), n=l (8 tiles), K=Lq]
    tgemm<false, false, true, false, 3><<<dim3(8, 1, B_), 256>>>(
        Q, LQ, (long)D_ * LQ,  pE, LQ, (long)LC * LQ,
        pAt, LC, (long)D_ * LC,  LQ,
        qmask, LQ,  nullptr, 0,  nullptr, nullptr,  prv, LC);

    // G4: Bv^T[d][l] = (sum_m' T(m',d)*E(l,m')) * rinv(l)   [m=d, n=l (8 tiles), K=Lq]
    // A = T^T (AT, ld D_); B = E
    tgemm<true, false, false, false, 3><<<dim3(8, 1, B_), 256>>>(
        pT, D_, (long)LQ * D_,  pE, LQ, (long)LC * LQ,
        pBvt, LC, (long)D_ * LC,  LQ,
        nullptr, 0,  nullptr, 0,  nullptr, nullptr,  prv, LC);

    // output assembly (pure streaming)
    k_out<<<B_ * D_ * LC / 4 / 256, 256>>>(C, out);
}